// round 12
// baseline (speedup 1.0000x reference)
#include <cuda_runtime.h>
#include <cuda_fp16.h>
#include <math.h>
#include <stdint.h>

// ---------------- problem constants ----------------
#define T_TOK   8192
#define DIMK    1024
#define NE      31
#define TILE_M  128
#define SHBASE  28672
#define CAP     36864
#define MAXT_RT (SHBASE/TILE_M)   // 224
#define SHT     (T_TOK/TILE_M)    // 64
#define BN      128
#define BK      64
#define NCH     (DIMK/BK)         // 16
#define A_ST    16384
#define B_ST    16384
#define STG_B   (A_ST + B_ST)
#define DYN_SMEM (3*STG_B + 128)

// ---------------- device scratch ----------------
__device__ int    g_cnt[NE];
__device__ int    g_fill2[NE];
__device__ int    g_tok[SHBASE];
__device__ float  g_gate[SHBASE];
__device__ int    g_slot[T_TOK * 3];
__device__ int    g_tidx[T_TOK * 3];
__device__ float  g_tval[T_TOK * 3];
__device__ __half g_Hh[(size_t)CAP * DIMK];
__device__ __half g_Yh[(size_t)SHBASE * DIMK];
__device__ __half g_W1h[(size_t)32 * DIMK * DIMK];
__device__ __half g_W2h[(size_t)32 * DIMK * DIMK];
__device__ __half g_Xh[(size_t)T_TOK * DIMK];

__device__ __forceinline__ float gelu_exact(float v) {
    return 0.5f * v * (1.0f + erff(v * 0.70710678118654752f));
}
__device__ __forceinline__ uint32_t smem_u32(const void* p) {
    uint32_t a;
    asm("{ .reg .u64 t; cvta.to.shared.u64 t, %1; cvt.u32.u64 %0, t; }"
        : "=r"(a) : "l"(p));
    return a;
}
__device__ __forceinline__ void cpa16(uint32_t dst, const void* src, uint32_t sz) {
    asm volatile("cp.async.cg.shared.global [%0], [%1], 16, %2;\n"
                 :: "r"(dst), "l"(src), "r"(sz));
}
__device__ __forceinline__ void ldsm_x4(unsigned r[4], uint32_t a) {
    asm volatile("ldmatrix.sync.aligned.m8n8.x4.shared.b16 {%0,%1,%2,%3}, [%4];"
        : "=r"(r[0]), "=r"(r[1]), "=r"(r[2]), "=r"(r[3]) : "r"(a));
}
__device__ __forceinline__ void ldsm_x4t(unsigned r[4], uint32_t a) {
    asm volatile("ldmatrix.sync.aligned.m8n8.x4.trans.shared.b16 {%0,%1,%2,%3}, [%4];"
        : "=r"(r[0]), "=r"(r[1]), "=r"(r[2]), "=r"(r[3]) : "r"(a));
}
__device__ __forceinline__ void mma_f16(float c[4], const unsigned a[4],
                                        const unsigned b[2]) {
    asm volatile(
        "mma.sync.aligned.m16n8k16.row.col.f32.f16.f16.f32 "
        "{%0,%1,%2,%3}, {%4,%5,%6,%7}, {%8,%9}, {%0,%1,%2,%3};\n"
        : "+f"(c[0]), "+f"(c[1]), "+f"(c[2]), "+f"(c[3])
        : "r"(a[0]), "r"(a[1]), "r"(a[2]), "r"(a[3]), "r"(b[0]), "r"(b[1]));
}
__device__ __forceinline__ void cvt_store_h4(__half* dst, float4 v) {
    __half2 h0 = __floats2half2_rn(v.x, v.y);
    __half2 h1 = __floats2half2_rn(v.z, v.w);
    uint2 u = make_uint2(*(unsigned*)&h0, *(unsigned*)&h1);
    *(uint2*)dst = u;
}

// ---------------- init ----------------
__global__ void init_kernel() {
    int i = blockIdx.x * 256 + threadIdx.x;
    if (i < SHBASE) g_tok[i] = -1;
    if (i < NE) { g_cnt[i] = 0; g_fill2[i] = 0; }
}

// ---------------- convert x + shared W slices ----------------
__global__ __launch_bounds__(256) void conv_xsh_kernel(
    const float* __restrict__ x,
    const float* __restrict__ ws1, const float* __restrict__ ws2)
{
    size_t i = (size_t)blockIdx.x * 256 + threadIdx.x;
    const size_t NX = (size_t)T_TOK * DIMK / 4;
    const size_t NS = (size_t)DIMK * DIMK / 4;
    if (i < NX) {
        cvt_store_h4(g_Xh + i * 4, ((const float4*)x)[i]);
    } else if (i < NX + NS) {
        size_t j = i - NX;
        cvt_store_h4(g_W1h + ((size_t)NE * DIMK * DIMK) + j * 4,
                     ((const float4*)ws1)[j]);
    } else if (i < NX + 2 * NS) {
        size_t j = i - NX - NS;
        cvt_store_h4(g_W2h + ((size_t)NE * DIMK * DIMK) + j * 4,
                     ((const float4*)ws2)[j]);
    }
}

// ---------------- convert routed weights ----------------
__global__ __launch_bounds__(256) void conv_w1rt_kernel(const float* __restrict__ We1) {
    size_t j = (size_t)blockIdx.x * 256 + threadIdx.x;
    if (j >= (size_t)NE * DIMK * DIMK / 4) return;
    cvt_store_h4(g_W1h + j * 4, ((const float4*)We1)[j]);
}
__global__ __launch_bounds__(256) void conv_w2rt_kernel(const float* __restrict__ We2) {
    size_t j = (size_t)blockIdx.x * 256 + threadIdx.x;
    if (j >= (size_t)NE * DIMK * DIMK / 4) return;
    cvt_store_h4(g_W2h + j * 4, ((const float4*)We2)[j]);
}

// ---------------- router: float4 LDS, 32 tokens/block, grid 256 ----------
__global__ __launch_bounds__(256) void router_kernel(
    const float* __restrict__ x, const float* __restrict__ Wr,
    const float* __restrict__ br)
{
    __shared__ float xs[32][68];    // [token][k], stride 68 (272B, 16B-aligned)
    __shared__ float wsT[32][68];   // [expert][k] transposed
    int tid  = threadIdx.x;
    int t0   = blockIdx.x * 32;
    int lane = tid & 31;
    int w8   = tid >> 5;            // warp: 4 tokens

    float acc[4] = {0.f, 0.f, 0.f, 0.f};

    for (int k0 = 0; k0 < DIMK; k0 += 64) {
        // stage xs: 32 tokens x 64 k = 512 float4
        #pragma unroll
        for (int i = 0; i < 2; ++i) {
            int fid = tid + i * 256;
            int tr  = fid >> 4;
            int kq  = (fid & 15) * 4;
            *(float4*)(&xs[tr][kq]) =
                *(const float4*)(x + (size_t)(t0 + tr) * DIMK + k0 + kq);
        }
        // stage wsT transposed: wsT[e][kk] = Wr[(k0+kk)*NE + e]
        #pragma unroll
        for (int i = 0; i < 8; ++i) {
            int fid = tid + i * 256;
            int kk  = fid >> 5;
            int ee  = fid & 31;
            wsT[ee][kk] = (ee < NE) ? Wr[(size_t)(k0 + kk) * NE + ee] : 0.f;
        }
        __syncthreads();
        #pragma unroll
        for (int q = 0; q < 16; ++q) {
            float4 wv = *(const float4*)(&wsT[lane][q * 4]);
            #pragma unroll
            for (int j = 0; j < 4; ++j) {
                float4 xv = *(const float4*)(&xs[w8 * 4 + j][q * 4]);
                acc[j] += xv.x * wv.x + xv.y * wv.y + xv.z * wv.z + xv.w * wv.w;
            }
        }
        __syncthreads();
    }

    float bias = (lane < NE) ? br[lane] : 0.f;

    #pragma unroll
    for (int j = 0; j < 4; ++j) {
        int t = t0 + w8 * 4 + j;
        float v = (lane < NE) ? (acc[j] + bias) : -3.0e38f;
        float m = v;
        #pragma unroll
        for (int o = 16; o; o >>= 1)
            m = fmaxf(m, __shfl_xor_sync(0xffffffffu, m, o));
        float p = expf(v - m);
        float s = p;
        #pragma unroll
        for (int o = 16; o; o >>= 1)
            s += __shfl_xor_sync(0xffffffffu, s, o);
        p /= s;
        float pv = p;
        #pragma unroll
        for (int r = 0; r < 3; ++r) {
            float mv = pv; int mi = lane;
            #pragma unroll
            for (int o = 16; o; o >>= 1) {
                float ov = __shfl_xor_sync(0xffffffffu, mv, o);
                int   oi = __shfl_xor_sync(0xffffffffu, mi, o);
                if (ov > mv || (ov == mv && oi < mi)) { mv = ov; mi = oi; }
            }
            if (lane == 0) {
                g_tidx[t * 3 + r] = mi;
                g_tval[t * 3 + r] = mv;
                atomicAdd(&g_cnt[mi], 1);
            }
            if (lane == mi) pv = -1.f;
        }
    }
}

// ---------------- fill ----------------
__global__ __launch_bounds__(256) void fill_kernel() {
    __shared__ int base[NE];
    if (threadIdx.x == 0) {
        int off = 0;
        for (int e = 0; e < NE; ++e) {
            base[e] = off;
            off += ((g_cnt[e] + TILE_M - 1) >> 7) << 7;
        }
    }
    __syncthreads();
    int t = blockIdx.x * 256 + threadIdx.x;
    if (t >= T_TOK) return;
    #pragma unroll
    for (int r = 0; r < 3; ++r) {
        int e   = g_tidx[t * 3 + r];
        int pos = base[e] + atomicAdd(&g_fill2[e], 1);
        g_tok[pos]  = t;
        g_gate[pos] = g_tval[t * 3 + r];
        g_slot[t * 3 + r] = pos;
    }
}

// ---------------- FFN GEMM ----------------
#define LDFRAG(A_, B_, ksv) do {                                              \
    uint32_t ab_ = aLd + stO + aXor[ksv];                                     \
    _Pragma("unroll")                                                         \
    for (int mt_ = 0; mt_ < 4; ++mt_) ldsm_x4(A_[mt_], ab_ + mt_ * 2048);     \
    uint32_t bb_ = bLd + stO + (ksv) * 4096;                                  \
    _Pragma("unroll")                                                         \
    for (int np_ = 0; np_ < 4; ++np_) {                                       \
        unsigned r_[4];                                                       \
        ldsm_x4t(r_, bb_ + chnkB[np_]);                                       \
        B_[2*np_][0] = r_[0]; B_[2*np_][1] = r_[1];                           \
        B_[2*np_+1][0] = r_[2]; B_[2*np_+1][1] = r_[3];                       \
    }                                                                         \
} while (0)

#define MMAB(A_, B_) do {                                                     \
    _Pragma("unroll")                                                         \
    for (int mt_ = 0; mt_ < 4; ++mt_)                                         \
        _Pragma("unroll")                                                     \
        for (int nt_ = 0; nt_ < 8; ++nt_)                                     \
            mma_f16(acc[mt_][nt_], A_[mt_], B_[nt_]);                         \
} while (0)

#define ISSUE_CP(cpO_, k0_) do {                                              \
    uint32_t ad_ = smBase + (cpO_) + aD0;                                     \
    uint32_t bd_ = smBase + (cpO_) + bD0;                                     \
    _Pragma("unroll")                                                         \
    for (int i_ = 0; i_ < 8; ++i_)                                            \
        cpa16(ad_ + i_ * 2048, aP[i_] + (k0_),                                \
              ((aMask >> i_) & 1u) << 4);                                     \
    _Pragma("unroll")                                                         \
    for (int i_ = 0; i_ < 8; ++i_)                                            \
        cpa16(bd_ + i_ * 2048, bP + (size_t)((k0_) + 8 * i_) * DIMK, 16u);    \
    asm volatile("cp.async.commit_group;" ::: "memory");                      \
} while (0)

template <int MODE, int SH>
__global__ __launch_bounds__(128, 2) void ffn_kernel(
    const float* __restrict__ bsh, const float* __restrict__ Bex,
    const float* __restrict__ xp, float* __restrict__ outp)
{
    int tile = blockIdx.x;
    int e;
    if (SH) {
        e = NE;
    } else {
        int rem = tile;
        e = 0;
        #pragma unroll 1
        for (; e < NE; ++e) {
            int tl = (g_cnt[e] + TILE_M - 1) >> 7;
            if (rem < tl) break;
            rem -= tl;
        }
        if (e == NE) return;
    }
    const __half* W = (MODE == 0 ? g_W1h : g_W2h) + (size_t)e * DIMK * DIMK;
    const float* Bv = SH ? bsh : (Bex + (size_t)e * DIMK);
    const int rb  = (SH ? SHBASE : 0) + tile * TILE_M;
    const int nb0 = blockIdx.y * BN;

    extern __shared__ char smraw[];
    const uint32_t smBase = (smem_u32(smraw) + 127) & ~127u;

    const int tid  = threadIdx.x;
    const int lane = tid & 31;
    const int w    = tid >> 5;
    const int wm   = (w & 1) * 64;
    const int wn   = (w >> 1) * 64;
    const int qr   = lane >> 2;
    const int qc   = lane & 3;

    const int arow = tid >> 3;
    const int kb   = tid & 7;
    const __half* aP[8];
    uint32_t aMask = 0;
    #pragma unroll
    for (int i = 0; i < 8; ++i) {
        int row = arow + 16 * i;
        if (MODE == 0) {
            int tk = SH ? (tile * TILE_M + row) : g_tok[rb + row];
            aP[i] = g_Xh + (size_t)(tk < 0 ? 0 : tk) * DIMK + kb * 8;
            if (tk >= 0) aMask |= (1u << i);
        } else {
            aP[i] = g_Hh + (size_t)(rb + row) * DIMK + kb * 8;
            aMask |= (1u << i);
        }
    }
    const uint32_t aD0 = (uint32_t)(arow * 128) + ((uint32_t)(kb ^ (arow & 7)) << 4);
    const int bkr = tid >> 4;
    const int nc  = tid & 15;
    const __half* bP = W + (size_t)bkr * DIMK + nb0 + nc * 8;
    const uint32_t bD0 = (uint32_t)A_ST + (uint32_t)(bkr * 256)
                       + ((uint32_t)((nc & 8) | ((nc ^ (bkr & 7)) & 7)) << 4);

    const int lt = lane >> 3, lr = lane & 7;
    const int mB  = (lt & 1) * 8 + lr;
    const int kbt = lt >> 1;
    const int sA  = (wm + mB) & 7;
    const uint32_t aLd = smBase + (uint32_t)((wm + mB) * 128);
    const int kB  = (lt & 1) * 8 + lr;
    const int s2  = kB & 7;
    const int ncT = (wn >> 3) + (lt >> 1);
    const uint32_t bLd = smBase + A_ST + (uint32_t)(kB * 256);
    uint32_t aXor[4], chnkB[4];
    #pragma unroll
    for (int ks = 0; ks < 4; ++ks)
        aXor[ks] = (uint32_t)(((2 * ks + kbt) ^ sA) << 4);
    #pragma unroll
    for (int np = 0; np < 4; ++np) {
        int nc2 = ncT + 2 * np;
        chnkB[np] = (uint32_t)(((nc2 & 8) | ((nc2 ^ s2) & 7)) << 4);
    }

    float acc[4][8][4];
    #pragma unroll
    for (int mt = 0; mt < 4; ++mt)
        #pragma unroll
        for (int nt = 0; nt < 8; ++nt)
            #pragma unroll
            for (int q = 0; q < 4; ++q) acc[mt][nt][q] = 0.f;

    ISSUE_CP(0u, 0);
    ISSUE_CP((uint32_t)STG_B, BK);

    uint32_t stO = 0;
    int kNext = 2 * BK;
    for (int c = 0; c < NCH; ++c) {
        if (c < NCH - 1)
            asm volatile("cp.async.wait_group 1;" ::: "memory");
        else
            asm volatile("cp.async.wait_group 0;" ::: "memory");
        __syncthreads();

        unsigned a0[4][4], a1[4][4], b0[8][2], b1[8][2];
        LDFRAG(a0, b0, 0);

        if (c + 2 < NCH) {
            uint32_t cpO = (stO >= (uint32_t)STG_B) ? stO - (uint32_t)STG_B
                                                    : stO + 2u * (uint32_t)STG_B;
            ISSUE_CP(cpO, kNext);
            kNext += BK;
        } else {
            asm volatile("cp.async.commit_group;" ::: "memory");
        }

        LDFRAG(a1, b1, 1);
        MMAB(a0, b0);
        LDFRAG(a0, b0, 2);
        MMAB(a1, b1);
        LDFRAG(a1, b1, 3);
        MMAB(a0, b0);
        MMAB(a1, b1);

        stO = (stO == 2u * (uint32_t)STG_B) ? 0u : stO + (uint32_t)STG_B;
    }

    #pragma unroll
    for (int mt = 0; mt < 4; ++mt) {
        int r0 = rb + wm + mt * 16 + qr;
        int r1 = r0 + 8;
        float g0 = 1.f, g1 = 1.f;
        if (MODE == 1 && !SH) { g0 = g_gate[r0]; g1 = g_gate[r1]; }
        #pragma unroll
        for (int nt = 0; nt < 8; ++nt) {
            int gcol = nb0 + wn + nt * 8 + 2 * qc;
            float b0v = Bv[gcol];
            float b1v = Bv[gcol + 1];
            float c00 = acc[mt][nt][0] + b0v;
            float c01 = acc[mt][nt][1] + b1v;
            float c10 = acc[mt][nt][2] + b0v;
            float c11 = acc[mt][nt][3] + b1v;
            if (MODE == 0) {
                __half2 h0 = __floats2half2_rn(gelu_exact(c00), gelu_exact(c01));
                __half2 h1 = __floats2half2_rn(gelu_exact(c10), gelu_exact(c11));
                *(__half2*)(&g_Hh[(size_t)r0 * DIMK + gcol]) = h0;
                *(__half2*)(&g_Hh[(size_t)r1 * DIMK + gcol]) = h1;
            } else if (SH) {
                int tok0 = r0 - SHBASE, tok1 = r1 - SHBASE;
                float2 x0 = *(const float2*)(xp + (size_t)tok0 * DIMK + gcol);
                float2 x1 = *(const float2*)(xp + (size_t)tok1 * DIMK + gcol);
                float2 v0 = make_float2(x0.x + c00, x0.y + c01);
                float2 v1 = make_float2(x1.x + c10, x1.y + c11);
                *(float2*)(outp + (size_t)tok0 * DIMK + gcol) = v0;
                *(float2*)(outp + (size_t)tok1 * DIMK + gcol) = v1;
            } else {
                __half2 h0 = __floats2half2_rn(g0 * c00, g0 * c01);
                __half2 h1 = __floats2half2_rn(g1 * c10, g1 * c11);
                *(__half2*)(&g_Yh[(size_t)r0 * DIMK + gcol]) = h0;
                *(__half2*)(&g_Yh[(size_t)r1 * DIMK + gcol]) = h1;
            }
        }
    }
}

// ---------------- finalize ----------------
__global__ void finalize_kernel(float* __restrict__ out)
{
    int idx = blockIdx.x * 256 + threadIdx.x;
    int t = idx >> 8;
    int q = (idx & 255) * 4;
    float4 r = *(const float4*)(out + (size_t)t * DIMK + q);
    #pragma unroll
    for (int k = 0; k < 3; ++k) {
        int s = g_slot[t * 3 + k];
        uint2 u = *(const uint2*)(&g_Yh[(size_t)s * DIMK + q]);
        __half2 h0 = *(__half2*)&u.x;
        __half2 h1 = *(__half2*)&u.y;
        float2 f0 = __half22float2(h0);
        float2 f1 = __half22float2(h1);
        r.x += f0.x; r.y += f0.y; r.z += f1.x; r.w += f1.y;
    }
    *(float4*)(out + (size_t)t * DIMK + q) = r;
}

// ---------------- launch ----------------
extern "C" void kernel_launch(void* const* d_in, const int* in_sizes, int n_in,
                              void* d_out, int out_size)
{
    const float* x   = (const float*)d_in[0];
    const float* ws1 = (const float*)d_in[1];
    const float* bs1 = (const float*)d_in[2];
    const float* ws2 = (const float*)d_in[3];
    const float* bs2 = (const float*)d_in[4];
    const float* We1 = (const float*)d_in[5];
    const float* Be1 = (const float*)d_in[6];
    const float* We2 = (const float*)d_in[7];
    const float* Be2 = (const float*)d_in[8];
    const float* Wr  = (const float*)d_in[9];
    const float* br  = (const float*)d_in[10];
    float* out = (float*)d_out;

    static cudaStream_t sB = 0, sD = 0;
    static cudaEvent_t evRoot = 0, evXsh = 0, evW1rt = 0, evW2rt = 0, evRt = 0;
    static bool init_done = false;
    if (!init_done) {
        cudaFuncSetAttribute(ffn_kernel<0,0>,
                             cudaFuncAttributeMaxDynamicSharedMemorySize, DYN_SMEM);
        cudaFuncSetAttribute(ffn_kernel<1,0>,
                             cudaFuncAttributeMaxDynamicSharedMemorySize, DYN_SMEM);
        cudaFuncSetAttribute(ffn_kernel<0,1>,
                             cudaFuncAttributeMaxDynamicSharedMemorySize, DYN_SMEM);
        cudaFuncSetAttribute(ffn_kernel<1,1>,
                             cudaFuncAttributeMaxDynamicSharedMemorySize, DYN_SMEM);
        cudaStreamCreateWithFlags(&sB, cudaStreamNonBlocking);
        cudaStreamCreateWithFlags(&sD, cudaStreamNonBlocking);
        cudaEventCreateWithFlags(&evRoot, cudaEventDisableTiming);
        cudaEventCreateWithFlags(&evXsh, cudaEventDisableTiming);
        cudaEventCreateWithFlags(&evW1rt, cudaEventDisableTiming);
        cudaEventCreateWithFlags(&evW2rt, cudaEventDisableTiming);
        cudaEventCreateWithFlags(&evRt, cudaEventDisableTiming);
        init_done = true;
    }

    cudaEventRecord(evRoot, 0);
    cudaStreamWaitEvent(sB, evRoot, 0);
    cudaStreamWaitEvent(sD, evRoot, 0);

    // stream D: routed weight conversions
    {
        size_t nr = (size_t)NE * DIMK * DIMK / 4;
        conv_w1rt_kernel<<<(unsigned)((nr + 255) / 256), 256, 0, sD>>>(We1);
        cudaEventRecord(evW1rt, sD);
        conv_w2rt_kernel<<<(unsigned)((nr + 255) / 256), 256, 0, sD>>>(We2);
        cudaEventRecord(evW2rt, sD);
    }

    // stream B: routing chain
    init_kernel<<<(SHBASE + 255) / 256, 256, 0, sB>>>();
    router_kernel<<<T_TOK / 32, 256, 0, sB>>>(x, Wr, br);
    fill_kernel<<<T_TOK / 256, 256, 0, sB>>>();

    // main: x + shared slices, shared-expert FFN
    {
        size_t n4 = (size_t)T_TOK * DIMK / 4 + 2 * ((size_t)DIMK * DIMK / 4);
        conv_xsh_kernel<<<(unsigned)((n4 + 255) / 256), 256>>>(x, ws1, ws2);
    }
    cudaEventRecord(evXsh, 0);

    dim3 gSh(SHT, DIMK / BN);
    ffn_kernel<0,1><<<gSh, 128, DYN_SMEM>>>(bs1, Be1, x, out);
    ffn_kernel<1,1><<<gSh, 128, DYN_SMEM>>>(bs2, Be2, x, out);

    // stream B: routed FFNs
    cudaStreamWaitEvent(sB, evXsh, 0);
    cudaStreamWaitEvent(sB, evW1rt, 0);
    dim3 gRt(MAXT_RT, DIMK / BN);
    ffn_kernel<0,0><<<gRt, 128, DYN_SMEM, sB>>>(bs1, Be1, x, out);
    cudaStreamWaitEvent(sB, evW2rt, 0);
    ffn_kernel<1,0><<<gRt, 128, DYN_SMEM, sB>>>(bs2, Be2, x, out);
    cudaEventRecord(evRt, sB);

    // main: join routed, finalize
    cudaStreamWaitEvent(0, evRt, 0);
    finalize_kernel<<<T_TOK, 256>>>(out);
}

// round 13
// speedup vs baseline: 1.0410x; 1.0410x over previous
#include <cuda_runtime.h>
#include <cuda_fp16.h>
#include <math.h>
#include <stdint.h>

// ---------------- problem constants ----------------
#define T_TOK   8192
#define DIMK    1024
#define NE      31
#define TILE_M  128
#define SHBASE  28672
#define CAP     36864
#define MAXT_RT (SHBASE/TILE_M)   // 224
#define SHT     (T_TOK/TILE_M)    // 64
#define BN      128
#define BK      64
#define NCH     (DIMK/BK)         // 16
#define A_ST    16384
#define B_ST    16384
#define STG_B   (A_ST + B_ST)
#define DYN_SMEM (3*STG_B + 128)

// ---------------- device scratch ----------------
__device__ int    g_cnt[NE];
__device__ int    g_fill2[NE];
__device__ int    g_tok[SHBASE];
__device__ float  g_gate[SHBASE];
__device__ int    g_slot[T_TOK * 3];
__device__ int    g_tidx[T_TOK * 3];
__device__ float  g_tval[T_TOK * 3];
__device__ __half g_Hh[(size_t)CAP * DIMK];
__device__ __half g_Yh[(size_t)SHBASE * DIMK];
__device__ __half g_W1h[(size_t)32 * DIMK * DIMK];
__device__ __half g_W2h[(size_t)32 * DIMK * DIMK];
__device__ __half g_Xh[(size_t)T_TOK * DIMK];

__device__ __forceinline__ float gelu_exact(float v) {
    return 0.5f * v * (1.0f + erff(v * 0.70710678118654752f));
}
__device__ __forceinline__ uint32_t smem_u32(const void* p) {
    uint32_t a;
    asm("{ .reg .u64 t; cvta.to.shared.u64 t, %1; cvt.u32.u64 %0, t; }"
        : "=r"(a) : "l"(p));
    return a;
}
__device__ __forceinline__ void cpa16(uint32_t dst, const void* src, uint32_t sz) {
    asm volatile("cp.async.cg.shared.global [%0], [%1], 16, %2;\n"
                 :: "r"(dst), "l"(src), "r"(sz));
}
__device__ __forceinline__ void ldsm_x4(unsigned r[4], uint32_t a) {
    asm volatile("ldmatrix.sync.aligned.m8n8.x4.shared.b16 {%0,%1,%2,%3}, [%4];"
        : "=r"(r[0]), "=r"(r[1]), "=r"(r[2]), "=r"(r[3]) : "r"(a));
}
__device__ __forceinline__ void ldsm_x4t(unsigned r[4], uint32_t a) {
    asm volatile("ldmatrix.sync.aligned.m8n8.x4.trans.shared.b16 {%0,%1,%2,%3}, [%4];"
        : "=r"(r[0]), "=r"(r[1]), "=r"(r[2]), "=r"(r[3]) : "r"(a));
}
__device__ __forceinline__ void mma_f16(float c[4], const unsigned a[4],
                                        const unsigned b[2]) {
    asm volatile(
        "mma.sync.aligned.m16n8k16.row.col.f32.f16.f16.f32 "
        "{%0,%1,%2,%3}, {%4,%5,%6,%7}, {%8,%9}, {%0,%1,%2,%3};\n"
        : "+f"(c[0]), "+f"(c[1]), "+f"(c[2]), "+f"(c[3])
        : "r"(a[0]), "r"(a[1]), "r"(a[2]), "r"(a[3]), "r"(b[0]), "r"(b[1]));
}
__device__ __forceinline__ void cvt_store_h4(__half* dst, float4 v) {
    __half2 h0 = __floats2half2_rn(v.x, v.y);
    __half2 h1 = __floats2half2_rn(v.z, v.w);
    uint2 u = make_uint2(*(unsigned*)&h0, *(unsigned*)&h1);
    *(uint2*)dst = u;
}

// ---------------- init ----------------
__global__ void init_kernel() {
    int i = blockIdx.x * 256 + threadIdx.x;
    if (i < SHBASE) g_tok[i] = -1;
    if (i < NE) { g_cnt[i] = 0; g_fill2[i] = 0; }
}

// ---------------- convert x + shared W slices ----------------
__global__ __launch_bounds__(256) void conv_xsh_kernel(
    const float* __restrict__ x,
    const float* __restrict__ ws1, const float* __restrict__ ws2)
{
    size_t i = (size_t)blockIdx.x * 256 + threadIdx.x;
    const size_t NX = (size_t)T_TOK * DIMK / 4;
    const size_t NS = (size_t)DIMK * DIMK / 4;
    if (i < NX) {
        cvt_store_h4(g_Xh + i * 4, ((const float4*)x)[i]);
    } else if (i < NX + NS) {
        size_t j = i - NX;
        cvt_store_h4(g_W1h + ((size_t)NE * DIMK * DIMK) + j * 4,
                     ((const float4*)ws1)[j]);
    } else if (i < NX + 2 * NS) {
        size_t j = i - NX - NS;
        cvt_store_h4(g_W2h + ((size_t)NE * DIMK * DIMK) + j * 4,
                     ((const float4*)ws2)[j]);
    }
}

// ---------------- convert routed weights ----------------
__global__ __launch_bounds__(256) void conv_w1rt_kernel(const float* __restrict__ We1) {
    size_t j = (size_t)blockIdx.x * 256 + threadIdx.x;
    if (j >= (size_t)NE * DIMK * DIMK / 4) return;
    cvt_store_h4(g_W1h + j * 4, ((const float4*)We1)[j]);
}
__global__ __launch_bounds__(256) void conv_w2rt_kernel(const float* __restrict__ We2) {
    size_t j = (size_t)blockIdx.x * 256 + threadIdx.x;
    if (j >= (size_t)NE * DIMK * DIMK / 4) return;
    cvt_store_h4(g_W2h + j * 4, ((const float4*)We2)[j]);
}

// ---------------- router: 16 tokens/block, grid 512 (occupancy fix) ------
__global__ __launch_bounds__(256) void router_kernel(
    const float* __restrict__ x, const float* __restrict__ Wr,
    const float* __restrict__ br)
{
    __shared__ float xs[16][68];    // [token][k]
    __shared__ float wsT[32][68];   // [expert][k] transposed
    int tid  = threadIdx.x;
    int t0   = blockIdx.x * 16;
    int lane = tid & 31;
    int w8   = tid >> 5;            // warp: 2 tokens

    float acc[2] = {0.f, 0.f};

    for (int k0 = 0; k0 < DIMK; k0 += 64) {
        // stage xs: 16 tokens x 64 k = 256 float4 (1 per thread)
        {
            int tr = tid >> 4;
            int kq = (tid & 15) * 4;
            *(float4*)(&xs[tr][kq]) =
                *(const float4*)(x + (size_t)(t0 + tr) * DIMK + k0 + kq);
        }
        // stage wsT transposed: wsT[e][kk] = Wr[(k0+kk)*NE + e]
        #pragma unroll
        for (int i = 0; i < 8; ++i) {
            int fid = tid + i * 256;
            int kk  = fid >> 5;
            int ee  = fid & 31;
            wsT[ee][kk] = (ee < NE) ? Wr[(size_t)(k0 + kk) * NE + ee] : 0.f;
        }
        __syncthreads();
        #pragma unroll
        for (int q = 0; q < 16; ++q) {
            float4 wv = *(const float4*)(&wsT[lane][q * 4]);
            #pragma unroll
            for (int j = 0; j < 2; ++j) {
                float4 xv = *(const float4*)(&xs[w8 * 2 + j][q * 4]);
                acc[j] += xv.x * wv.x + xv.y * wv.y + xv.z * wv.z + xv.w * wv.w;
            }
        }
        __syncthreads();
    }

    float bias = (lane < NE) ? br[lane] : 0.f;

    #pragma unroll
    for (int j = 0; j < 2; ++j) {
        int t = t0 + w8 * 2 + j;
        float v = (lane < NE) ? (acc[j] + bias) : -3.0e38f;
        float m = v;
        #pragma unroll
        for (int o = 16; o; o >>= 1)
            m = fmaxf(m, __shfl_xor_sync(0xffffffffu, m, o));
        float p = expf(v - m);
        float s = p;
        #pragma unroll
        for (int o = 16; o; o >>= 1)
            s += __shfl_xor_sync(0xffffffffu, s, o);
        p /= s;
        float pv = p;
        #pragma unroll
        for (int r = 0; r < 3; ++r) {
            float mv = pv; int mi = lane;
            #pragma unroll
            for (int o = 16; o; o >>= 1) {
                float ov = __shfl_xor_sync(0xffffffffu, mv, o);
                int   oi = __shfl_xor_sync(0xffffffffu, mi, o);
                if (ov > mv || (ov == mv && oi < mi)) { mv = ov; mi = oi; }
            }
            if (lane == 0) {
                g_tidx[t * 3 + r] = mi;
                g_tval[t * 3 + r] = mv;
                atomicAdd(&g_cnt[mi], 1);
            }
            if (lane == mi) pv = -1.f;
        }
    }
}

// ---------------- fill ----------------
__global__ __launch_bounds__(256) void fill_kernel() {
    __shared__ int base[NE];
    if (threadIdx.x == 0) {
        int off = 0;
        for (int e = 0; e < NE; ++e) {
            base[e] = off;
            off += ((g_cnt[e] + TILE_M - 1) >> 7) << 7;
        }
    }
    __syncthreads();
    int t = blockIdx.x * 256 + threadIdx.x;
    if (t >= T_TOK) return;
    #pragma unroll
    for (int r = 0; r < 3; ++r) {
        int e   = g_tidx[t * 3 + r];
        int pos = base[e] + atomicAdd(&g_fill2[e], 1);
        g_tok[pos]  = t;
        g_gate[pos] = g_tval[t * 3 + r];
        g_slot[t * 3 + r] = pos;
    }
}

// ---------------- FFN GEMM ----------------
#define LDFRAG(A_, B_, ksv) do {                                              \
    uint32_t ab_ = aLd + stO + aXor[ksv];                                     \
    _Pragma("unroll")                                                         \
    for (int mt_ = 0; mt_ < 4; ++mt_) ldsm_x4(A_[mt_], ab_ + mt_ * 2048);     \
    uint32_t bb_ = bLd + stO + (ksv) * 4096;                                  \
    _Pragma("unroll")                                                         \
    for (int np_ = 0; np_ < 4; ++np_) {                                       \
        unsigned r_[4];                                                       \
        ldsm_x4t(r_, bb_ + chnkB[np_]);                                       \
        B_[2*np_][0] = r_[0]; B_[2*np_][1] = r_[1];                           \
        B_[2*np_+1][0] = r_[2]; B_[2*np_+1][1] = r_[3];                       \
    }                                                                         \
} while (0)

#define MMAB(A_, B_) do {                                                     \
    _Pragma("unroll")                                                         \
    for (int mt_ = 0; mt_ < 4; ++mt_)                                         \
        _Pragma("unroll")                                                     \
        for (int nt_ = 0; nt_ < 8; ++nt_)                                     \
            mma_f16(acc[mt_][nt_], A_[mt_], B_[nt_]);                         \
} while (0)

#define ISSUE_CP(cpO_, k0_) do {                                              \
    uint32_t ad_ = smBase + (cpO_) + aD0;                                     \
    uint32_t bd_ = smBase + (cpO_) + bD0;                                     \
    _Pragma("unroll")                                                         \
    for (int i_ = 0; i_ < 8; ++i_)                                            \
        cpa16(ad_ + i_ * 2048, aP[i_] + (k0_),                                \
              ((aMask >> i_) & 1u) << 4);                                     \
    _Pragma("unroll")                                                         \
    for (int i_ = 0; i_ < 8; ++i_)                                            \
        cpa16(bd_ + i_ * 2048, bP + (size_t)((k0_) + 8 * i_) * DIMK, 16u);    \
    asm volatile("cp.async.commit_group;" ::: "memory");                      \
} while (0)

template <int MODE, int SH>
__global__ __launch_bounds__(128, 2) void ffn_kernel(
    const float* __restrict__ bsh, const float* __restrict__ Bex,
    const float* __restrict__ xp, float* __restrict__ outp)
{
    int tile = blockIdx.x;
    int e;
    if (SH) {
        e = NE;
    } else {
        int rem = tile;
        e = 0;
        #pragma unroll 1
        for (; e < NE; ++e) {
            int tl = (g_cnt[e] + TILE_M - 1) >> 7;
            if (rem < tl) break;
            rem -= tl;
        }
        if (e == NE) return;
    }
    const __half* W = (MODE == 0 ? g_W1h : g_W2h) + (size_t)e * DIMK * DIMK;
    const float* Bv = SH ? bsh : (Bex + (size_t)e * DIMK);
    const int rb  = (SH ? SHBASE : 0) + tile * TILE_M;
    const int nb0 = blockIdx.y * BN;

    extern __shared__ char smraw[];
    const uint32_t smBase = (smem_u32(smraw) + 127) & ~127u;

    const int tid  = threadIdx.x;
    const int lane = tid & 31;
    const int w    = tid >> 5;
    const int wm   = (w & 1) * 64;
    const int wn   = (w >> 1) * 64;
    const int qr   = lane >> 2;
    const int qc   = lane & 3;

    const int arow = tid >> 3;
    const int kb   = tid & 7;
    const __half* aP[8];
    uint32_t aMask = 0;
    #pragma unroll
    for (int i = 0; i < 8; ++i) {
        int row = arow + 16 * i;
        if (MODE == 0) {
            int tk = SH ? (tile * TILE_M + row) : g_tok[rb + row];
            aP[i] = g_Xh + (size_t)(tk < 0 ? 0 : tk) * DIMK + kb * 8;
            if (tk >= 0) aMask |= (1u << i);
        } else {
            aP[i] = g_Hh + (size_t)(rb + row) * DIMK + kb * 8;
            aMask |= (1u << i);
        }
    }
    const uint32_t aD0 = (uint32_t)(arow * 128) + ((uint32_t)(kb ^ (arow & 7)) << 4);
    const int bkr = tid >> 4;
    const int nc  = tid & 15;
    const __half* bP = W + (size_t)bkr * DIMK + nb0 + nc * 8;
    const uint32_t bD0 = (uint32_t)A_ST + (uint32_t)(bkr * 256)
                       + ((uint32_t)((nc & 8) | ((nc ^ (bkr & 7)) & 7)) << 4);

    const int lt = lane >> 3, lr = lane & 7;
    const int mB  = (lt & 1) * 8 + lr;
    const int kbt = lt >> 1;
    const int sA  = (wm + mB) & 7;
    const uint32_t aLd = smBase + (uint32_t)((wm + mB) * 128);
    const int kB  = (lt & 1) * 8 + lr;
    const int s2  = kB & 7;
    const int ncT = (wn >> 3) + (lt >> 1);
    const uint32_t bLd = smBase + A_ST + (uint32_t)(kB * 256);
    uint32_t aXor[4], chnkB[4];
    #pragma unroll
    for (int ks = 0; ks < 4; ++ks)
        aXor[ks] = (uint32_t)(((2 * ks + kbt) ^ sA) << 4);
    #pragma unroll
    for (int np = 0; np < 4; ++np) {
        int nc2 = ncT + 2 * np;
        chnkB[np] = (uint32_t)(((nc2 & 8) | ((nc2 ^ s2) & 7)) << 4);
    }

    float acc[4][8][4];
    #pragma unroll
    for (int mt = 0; mt < 4; ++mt)
        #pragma unroll
        for (int nt = 0; nt < 8; ++nt)
            #pragma unroll
            for (int q = 0; q < 4; ++q) acc[mt][nt][q] = 0.f;

    ISSUE_CP(0u, 0);
    ISSUE_CP((uint32_t)STG_B, BK);

    uint32_t stO = 0;
    int kNext = 2 * BK;
    for (int c = 0; c < NCH; ++c) {
        if (c < NCH - 1)
            asm volatile("cp.async.wait_group 1;" ::: "memory");
        else
            asm volatile("cp.async.wait_group 0;" ::: "memory");
        __syncthreads();

        unsigned a0[4][4], a1[4][4], b0[8][2], b1[8][2];
        LDFRAG(a0, b0, 0);

        if (c + 2 < NCH) {
            uint32_t cpO = (stO >= (uint32_t)STG_B) ? stO - (uint32_t)STG_B
                                                    : stO + 2u * (uint32_t)STG_B;
            ISSUE_CP(cpO, kNext);
            kNext += BK;
        } else {
            asm volatile("cp.async.commit_group;" ::: "memory");
        }

        LDFRAG(a1, b1, 1);
        MMAB(a0, b0);
        LDFRAG(a0, b0, 2);
        MMAB(a1, b1);
        LDFRAG(a1, b1, 3);
        MMAB(a0, b0);
        MMAB(a1, b1);

        stO = (stO == 2u * (uint32_t)STG_B) ? 0u : stO + (uint32_t)STG_B;
    }

    #pragma unroll
    for (int mt = 0; mt < 4; ++mt) {
        int r0 = rb + wm + mt * 16 + qr;
        int r1 = r0 + 8;
        float g0 = 1.f, g1 = 1.f;
        if (MODE == 1 && !SH) { g0 = g_gate[r0]; g1 = g_gate[r1]; }
        #pragma unroll
        for (int nt = 0; nt < 8; ++nt) {
            int gcol = nb0 + wn + nt * 8 + 2 * qc;
            float b0v = Bv[gcol];
            float b1v = Bv[gcol + 1];
            float c00 = acc[mt][nt][0] + b0v;
            float c01 = acc[mt][nt][1] + b1v;
            float c10 = acc[mt][nt][2] + b0v;
            float c11 = acc[mt][nt][3] + b1v;
            if (MODE == 0) {
                __half2 h0 = __floats2half2_rn(gelu_exact(c00), gelu_exact(c01));
                __half2 h1 = __floats2half2_rn(gelu_exact(c10), gelu_exact(c11));
                *(__half2*)(&g_Hh[(size_t)r0 * DIMK + gcol]) = h0;
                *(__half2*)(&g_Hh[(size_t)r1 * DIMK + gcol]) = h1;
            } else if (SH) {
                int tok0 = r0 - SHBASE, tok1 = r1 - SHBASE;
                float2 x0 = *(const float2*)(xp + (size_t)tok0 * DIMK + gcol);
                float2 x1 = *(const float2*)(xp + (size_t)tok1 * DIMK + gcol);
                float2 v0 = make_float2(x0.x + c00, x0.y + c01);
                float2 v1 = make_float2(x1.x + c10, x1.y + c11);
                *(float2*)(outp + (size_t)tok0 * DIMK + gcol) = v0;
                *(float2*)(outp + (size_t)tok1 * DIMK + gcol) = v1;
            } else {
                __half2 h0 = __floats2half2_rn(g0 * c00, g0 * c01);
                __half2 h1 = __floats2half2_rn(g1 * c10, g1 * c11);
                *(__half2*)(&g_Yh[(size_t)r0 * DIMK + gcol]) = h0;
                *(__half2*)(&g_Yh[(size_t)r1 * DIMK + gcol]) = h1;
            }
        }
    }
}

// ---------------- finalize ----------------
__global__ void finalize_kernel(float* __restrict__ out)
{
    int idx = blockIdx.x * 256 + threadIdx.x;
    int t = idx >> 8;
    int q = (idx & 255) * 4;
    float4 r = *(const float4*)(out + (size_t)t * DIMK + q);
    #pragma unroll
    for (int k = 0; k < 3; ++k) {
        int s = g_slot[t * 3 + k];
        uint2 u = *(const uint2*)(&g_Yh[(size_t)s * DIMK + q]);
        __half2 h0 = *(__half2*)&u.x;
        __half2 h1 = *(__half2*)&u.y;
        float2 f0 = __half22float2(h0);
        float2 f1 = __half22float2(h1);
        r.x += f0.x; r.y += f0.y; r.z += f1.x; r.w += f1.y;
    }
    *(float4*)(out + (size_t)t * DIMK + q) = r;
}

// ---------------- launch ----------------
extern "C" void kernel_launch(void* const* d_in, const int* in_sizes, int n_in,
                              void* d_out, int out_size)
{
    const float* x   = (const float*)d_in[0];
    const float* ws1 = (const float*)d_in[1];
    const float* bs1 = (const float*)d_in[2];
    const float* ws2 = (const float*)d_in[3];
    const float* bs2 = (const float*)d_in[4];
    const float* We1 = (const float*)d_in[5];
    const float* Be1 = (const float*)d_in[6];
    const float* We2 = (const float*)d_in[7];
    const float* Be2 = (const float*)d_in[8];
    const float* Wr  = (const float*)d_in[9];
    const float* br  = (const float*)d_in[10];
    float* out = (float*)d_out;

    static cudaStream_t sB = 0, sD = 0;
    static cudaEvent_t evRoot = 0, evXsh = 0, evW1rt = 0, evW2rt = 0, evRt = 0;
    static bool init_done = false;
    if (!init_done) {
        cudaFuncSetAttribute(ffn_kernel<0,0>,
                             cudaFuncAttributeMaxDynamicSharedMemorySize, DYN_SMEM);
        cudaFuncSetAttribute(ffn_kernel<1,0>,
                             cudaFuncAttributeMaxDynamicSharedMemorySize, DYN_SMEM);
        cudaFuncSetAttribute(ffn_kernel<0,1>,
                             cudaFuncAttributeMaxDynamicSharedMemorySize, DYN_SMEM);
        cudaFuncSetAttribute(ffn_kernel<1,1>,
                             cudaFuncAttributeMaxDynamicSharedMemorySize, DYN_SMEM);
        cudaStreamCreateWithFlags(&sB, cudaStreamNonBlocking);
        cudaStreamCreateWithFlags(&sD, cudaStreamNonBlocking);
        cudaEventCreateWithFlags(&evRoot, cudaEventDisableTiming);
        cudaEventCreateWithFlags(&evXsh, cudaEventDisableTiming);
        cudaEventCreateWithFlags(&evW1rt, cudaEventDisableTiming);
        cudaEventCreateWithFlags(&evW2rt, cudaEventDisableTiming);
        cudaEventCreateWithFlags(&evRt, cudaEventDisableTiming);
        init_done = true;
    }

    cudaEventRecord(evRoot, 0);
    cudaStreamWaitEvent(sB, evRoot, 0);
    cudaStreamWaitEvent(sD, evRoot, 0);

    // stream D: routed weight conversions
    {
        size_t nr = (size_t)NE * DIMK * DIMK / 4;
        conv_w1rt_kernel<<<(unsigned)((nr + 255) / 256), 256, 0, sD>>>(We1);
        cudaEventRecord(evW1rt, sD);
        conv_w2rt_kernel<<<(unsigned)((nr + 255) / 256), 256, 0, sD>>>(We2);
        cudaEventRecord(evW2rt, sD);
    }

    // stream B: routing chain
    init_kernel<<<(SHBASE + 255) / 256, 256, 0, sB>>>();
    router_kernel<<<T_TOK / 16, 256, 0, sB>>>(x, Wr, br);
    fill_kernel<<<T_TOK / 256, 256, 0, sB>>>();

    // main: x + shared slices, shared-expert FFN
    {
        size_t n4 = (size_t)T_TOK * DIMK / 4 + 2 * ((size_t)DIMK * DIMK / 4);
        conv_xsh_kernel<<<(unsigned)((n4 + 255) / 256), 256>>>(x, ws1, ws2);
    }
    cudaEventRecord(evXsh, 0);

    dim3 gSh(SHT, DIMK / BN);
    ffn_kernel<0,1><<<gSh, 128, DYN_SMEM>>>(bs1, Be1, x, out);
    ffn_kernel<1,1><<<gSh, 128, DYN_SMEM>>>(bs2, Be2, x, out);

    // stream B: routed FFNs
    cudaStreamWaitEvent(sB, evXsh, 0);
    cudaStreamWaitEvent(sB, evW1rt, 0);
    dim3 gRt(MAXT_RT, DIMK / BN);
    ffn_kernel<0,0><<<gRt, 128, DYN_SMEM, sB>>>(bs1, Be1, x, out);
    cudaStreamWaitEvent(sB, evW2rt, 0);
    ffn_kernel<1,0><<<gRt, 128, DYN_SMEM, sB>>>(bs2, Be2, x, out);
    cudaEventRecord(evRt, sB);

    // main: join routed, finalize
    cudaStreamWaitEvent(0, evRt, 0);
    finalize_kernel<<<T_TOK, 256>>>(out);
}

// round 14
// speedup vs baseline: 1.0757x; 1.0333x over previous
#include <cuda_runtime.h>
#include <cuda_fp16.h>
#include <math.h>
#include <stdint.h>

// ---------------- problem constants ----------------
#define T_TOK   8192
#define DIMK    1024
#define NE      31
#define TILE_M  128
#define SHBASE  28672
#define CAP     36864
#define MAXT_RT (SHBASE/TILE_M)   // 224
#define SHT     (T_TOK/TILE_M)    // 64
#define BN      128
#define BK      64
#define NCH     (DIMK/BK)         // 16
#define A_ST    16384
#define B_ST    16384
#define STG_B   (A_ST + B_ST)
#define DYN_SMEM (3*STG_B + 128)

// ---------------- device scratch ----------------
__device__ int    g_cnt[NE];
__device__ int    g_fill2[NE];
__device__ int    g_tok[SHBASE];
__device__ float  g_gate[SHBASE];
__device__ int    g_slot[T_TOK * 3];
__device__ int    g_tidx[T_TOK * 3];
__device__ float  g_tval[T_TOK * 3];
__device__ __half g_Hh[(size_t)CAP * DIMK];
__device__ __half g_Yh[(size_t)SHBASE * DIMK];
__device__ __half g_W1h[(size_t)32 * DIMK * DIMK];
__device__ __half g_W2h[(size_t)32 * DIMK * DIMK];
__device__ __half g_Xh[(size_t)T_TOK * DIMK];

__device__ __forceinline__ float gelu_exact(float v) {
    return 0.5f * v * (1.0f + erff(v * 0.70710678118654752f));
}
__device__ __forceinline__ uint32_t smem_u32(const void* p) {
    uint32_t a;
    asm("{ .reg .u64 t; cvta.to.shared.u64 t, %1; cvt.u32.u64 %0, t; }"
        : "=r"(a) : "l"(p));
    return a;
}
__device__ __forceinline__ void cpa16(uint32_t dst, const void* src, uint32_t sz) {
    asm volatile("cp.async.cg.shared.global [%0], [%1], 16, %2;\n"
                 :: "r"(dst), "l"(src), "r"(sz));
}
__device__ __forceinline__ void ldsm_x4(unsigned r[4], uint32_t a) {
    asm volatile("ldmatrix.sync.aligned.m8n8.x4.shared.b16 {%0,%1,%2,%3}, [%4];"
        : "=r"(r[0]), "=r"(r[1]), "=r"(r[2]), "=r"(r[3]) : "r"(a));
}
__device__ __forceinline__ void ldsm_x4t(unsigned r[4], uint32_t a) {
    asm volatile("ldmatrix.sync.aligned.m8n8.x4.trans.shared.b16 {%0,%1,%2,%3}, [%4];"
        : "=r"(r[0]), "=r"(r[1]), "=r"(r[2]), "=r"(r[3]) : "r"(a));
}
__device__ __forceinline__ void mma_f16(float c[4], const unsigned a[4],
                                        const unsigned b[2]) {
    asm volatile(
        "mma.sync.aligned.m16n8k16.row.col.f32.f16.f16.f32 "
        "{%0,%1,%2,%3}, {%4,%5,%6,%7}, {%8,%9}, {%0,%1,%2,%3};\n"
        : "+f"(c[0]), "+f"(c[1]), "+f"(c[2]), "+f"(c[3])
        : "r"(a[0]), "r"(a[1]), "r"(a[2]), "r"(a[3]), "r"(b[0]), "r"(b[1]));
}
__device__ __forceinline__ void cvt_store_h4(__half* dst, float4 v) {
    __half2 h0 = __floats2half2_rn(v.x, v.y);
    __half2 h1 = __floats2half2_rn(v.z, v.w);
    uint2 u = make_uint2(*(unsigned*)&h0, *(unsigned*)&h1);
    *(uint2*)dst = u;
}

// ---------------- init ----------------
__global__ void init_kernel() {
    int i = blockIdx.x * 256 + threadIdx.x;
    if (i < SHBASE) g_tok[i] = -1;
    if (i < NE) { g_cnt[i] = 0; g_fill2[i] = 0; }
}

// ---------------- convert x + shared W slices ----------------
__global__ __launch_bounds__(256) void conv_xsh_kernel(
    const float* __restrict__ x,
    const float* __restrict__ ws1, const float* __restrict__ ws2)
{
    size_t i = (size_t)blockIdx.x * 256 + threadIdx.x;
    const size_t NX = (size_t)T_TOK * DIMK / 4;
    const size_t NS = (size_t)DIMK * DIMK / 4;
    if (i < NX) {
        cvt_store_h4(g_Xh + i * 4, ((const float4*)x)[i]);
    } else if (i < NX + NS) {
        size_t j = i - NX;
        cvt_store_h4(g_W1h + ((size_t)NE * DIMK * DIMK) + j * 4,
                     ((const float4*)ws1)[j]);
    } else if (i < NX + 2 * NS) {
        size_t j = i - NX - NS;
        cvt_store_h4(g_W2h + ((size_t)NE * DIMK * DIMK) + j * 4,
                     ((const float4*)ws2)[j]);
    }
}

// ---------------- convert routed weights ----------------
__global__ __launch_bounds__(256) void conv_w1rt_kernel(const float* __restrict__ We1) {
    size_t j = (size_t)blockIdx.x * 256 + threadIdx.x;
    if (j >= (size_t)NE * DIMK * DIMK / 4) return;
    cvt_store_h4(g_W1h + j * 4, ((const float4*)We1)[j]);
}
__global__ __launch_bounds__(256) void conv_w2rt_kernel(const float* __restrict__ We2) {
    size_t j = (size_t)blockIdx.x * 256 + threadIdx.x;
    if (j >= (size_t)NE * DIMK * DIMK / 4) return;
    cvt_store_h4(g_W2h + j * 4, ((const float4*)We2)[j]);
}

// ---------------- router: k-sliced warps, weights from gmem/L2 ----------
// 16 tokens/block, grid 512. Warp w owns k = r*64 + w*8 + [0,8) per round r.
__global__ __launch_bounds__(256) void router_kernel(
    const float* __restrict__ x, const float* __restrict__ Wr,
    const float* __restrict__ br)
{
    __shared__ float xs[16][68];      // staged x: 16 tokens x 64 k per round
    __shared__ float red[8][16][33];  // per-warp partial logits
    __shared__ float ls[16][33];      // reduced logits

    int tid  = threadIdx.x;
    int lane = tid & 31;
    int w    = tid >> 5;
    int t0   = blockIdx.x * 16;

    float acc[16];
    #pragma unroll
    for (int t = 0; t < 16; ++t) acc[t] = 0.f;

    const float* wp = Wr + lane;      // expert column (lane 31 unused)

    for (int r = 0; r < 16; ++r) {
        int k0 = r * 64;
        {   // stage xs: one float4 per thread, coalesced
            int tr = tid >> 4;
            int kq = (tid & 15) * 4;
            *(float4*)(&xs[tr][kq]) =
                *(const float4*)(x + (size_t)(t0 + tr) * DIMK + k0 + kq);
        }
        __syncthreads();

        // lane's 8 weights for this warp's k-slice (coalesced across lanes)
        float wreg[8];
        #pragma unroll
        for (int i = 0; i < 8; ++i)
            wreg[i] = (lane < NE)
                ? wp[(size_t)(k0 + w * 8 + i) * NE] : 0.f;

        #pragma unroll
        for (int q = 0; q < 2; ++q) {
            #pragma unroll
            for (int t = 0; t < 16; ++t) {
                float4 xv = *(const float4*)(&xs[t][w * 8 + q * 4]);
                acc[t] += xv.x * wreg[q * 4 + 0] + xv.y * wreg[q * 4 + 1]
                        + xv.z * wreg[q * 4 + 2] + xv.w * wreg[q * 4 + 3];
            }
        }
        __syncthreads();
    }

    // write partials, reduce across warps (fixed order -> deterministic)
    #pragma unroll
    for (int t = 0; t < 16; ++t) red[w][t][lane] = acc[t];
    __syncthreads();
    #pragma unroll
    for (int eidx = tid; eidx < 512; eidx += 256) {
        int t = eidx >> 5, e = eidx & 31;
        float s = 0.f;
        #pragma unroll
        for (int ww = 0; ww < 8; ++ww) s += red[ww][t][e];
        ls[t][e] = s;
    }
    __syncthreads();

    float bias = (lane < NE) ? br[lane] : 0.f;

    #pragma unroll
    for (int j = 0; j < 2; ++j) {
        int t = t0 + w * 2 + j;
        float v = (lane < NE) ? (ls[w * 2 + j][lane] + bias) : -3.0e38f;
        float m = v;
        #pragma unroll
        for (int o = 16; o; o >>= 1)
            m = fmaxf(m, __shfl_xor_sync(0xffffffffu, m, o));
        float p = expf(v - m);
        float s = p;
        #pragma unroll
        for (int o = 16; o; o >>= 1)
            s += __shfl_xor_sync(0xffffffffu, s, o);
        p /= s;
        float pv = p;
        #pragma unroll
        for (int r = 0; r < 3; ++r) {
            float mv = pv; int mi = lane;
            #pragma unroll
            for (int o = 16; o; o >>= 1) {
                float ov = __shfl_xor_sync(0xffffffffu, mv, o);
                int   oi = __shfl_xor_sync(0xffffffffu, mi, o);
                if (ov > mv || (ov == mv && oi < mi)) { mv = ov; mi = oi; }
            }
            if (lane == 0) {
                g_tidx[t * 3 + r] = mi;
                g_tval[t * 3 + r] = mv;
                atomicAdd(&g_cnt[mi], 1);
            }
            if (lane == mi) pv = -1.f;
        }
    }
}

// ---------------- fill ----------------
__global__ __launch_bounds__(256) void fill_kernel() {
    __shared__ int base[NE];
    if (threadIdx.x == 0) {
        int off = 0;
        for (int e = 0; e < NE; ++e) {
            base[e] = off;
            off += ((g_cnt[e] + TILE_M - 1) >> 7) << 7;
        }
    }
    __syncthreads();
    int t = blockIdx.x * 256 + threadIdx.x;
    if (t >= T_TOK) return;
    #pragma unroll
    for (int r = 0; r < 3; ++r) {
        int e   = g_tidx[t * 3 + r];
        int pos = base[e] + atomicAdd(&g_fill2[e], 1);
        g_tok[pos]  = t;
        g_gate[pos] = g_tval[t * 3 + r];
        g_slot[t * 3 + r] = pos;
    }
}

// ---------------- FFN GEMM ----------------
#define LDFRAG(A_, B_, ksv) do {                                              \
    uint32_t ab_ = aLd + stO + aXor[ksv];                                     \
    _Pragma("unroll")                                                         \
    for (int mt_ = 0; mt_ < 4; ++mt_) ldsm_x4(A_[mt_], ab_ + mt_ * 2048);     \
    uint32_t bb_ = bLd + stO + (ksv) * 4096;                                  \
    _Pragma("unroll")                                                         \
    for (int np_ = 0; np_ < 4; ++np_) {                                       \
        unsigned r_[4];                                                       \
        ldsm_x4t(r_, bb_ + chnkB[np_]);                                       \
        B_[2*np_][0] = r_[0]; B_[2*np_][1] = r_[1];                           \
        B_[2*np_+1][0] = r_[2]; B_[2*np_+1][1] = r_[3];                       \
    }                                                                         \
} while (0)

#define MMAB(A_, B_) do {                                                     \
    _Pragma("unroll")                                                         \
    for (int mt_ = 0; mt_ < 4; ++mt_)                                         \
        _Pragma("unroll")                                                     \
        for (int nt_ = 0; nt_ < 8; ++nt_)                                     \
            mma_f16(acc[mt_][nt_], A_[mt_], B_[nt_]);                         \
} while (0)

#define ISSUE_CP(cpO_, k0_) do {                                              \
    uint32_t ad_ = smBase + (cpO_) + aD0;                                     \
    uint32_t bd_ = smBase + (cpO_) + bD0;                                     \
    _Pragma("unroll")                                                         \
    for (int i_ = 0; i_ < 8; ++i_)                                            \
        cpa16(ad_ + i_ * 2048, aP[i_] + (k0_),                                \
              ((aMask >> i_) & 1u) << 4);                                     \
    _Pragma("unroll")                                                         \
    for (int i_ = 0; i_ < 8; ++i_)                                            \
        cpa16(bd_ + i_ * 2048, bP + (size_t)((k0_) + 8 * i_) * DIMK, 16u);    \
    asm volatile("cp.async.commit_group;" ::: "memory");                      \
} while (0)

template <int MODE, int SH>
__global__ __launch_bounds__(128, 2) void ffn_kernel(
    const float* __restrict__ bsh, const float* __restrict__ Bex,
    const float* __restrict__ xp, float* __restrict__ outp)
{
    int tile = blockIdx.x;
    int e;
    if (SH) {
        e = NE;
    } else {
        int rem = tile;
        e = 0;
        #pragma unroll 1
        for (; e < NE; ++e) {
            int tl = (g_cnt[e] + TILE_M - 1) >> 7;
            if (rem < tl) break;
            rem -= tl;
        }
        if (e == NE) return;
    }
    const __half* W = (MODE == 0 ? g_W1h : g_W2h) + (size_t)e * DIMK * DIMK;
    const float* Bv = SH ? bsh : (Bex + (size_t)e * DIMK);
    const int rb  = (SH ? SHBASE : 0) + tile * TILE_M;
    const int nb0 = blockIdx.y * BN;

    extern __shared__ char smraw[];
    const uint32_t smBase = (smem_u32(smraw) + 127) & ~127u;

    const int tid  = threadIdx.x;
    const int lane = tid & 31;
    const int w    = tid >> 5;
    const int wm   = (w & 1) * 64;
    const int wn   = (w >> 1) * 64;
    const int qr   = lane >> 2;
    const int qc   = lane & 3;

    const int arow = tid >> 3;
    const int kb   = tid & 7;
    const __half* aP[8];
    uint32_t aMask = 0;
    #pragma unroll
    for (int i = 0; i < 8; ++i) {
        int row = arow + 16 * i;
        if (MODE == 0) {
            int tk = SH ? (tile * TILE_M + row) : g_tok[rb + row];
            aP[i] = g_Xh + (size_t)(tk < 0 ? 0 : tk) * DIMK + kb * 8;
            if (tk >= 0) aMask |= (1u << i);
        } else {
            aP[i] = g_Hh + (size_t)(rb + row) * DIMK + kb * 8;
            aMask |= (1u << i);
        }
    }
    const uint32_t aD0 = (uint32_t)(arow * 128) + ((uint32_t)(kb ^ (arow & 7)) << 4);
    const int bkr = tid >> 4;
    const int nc  = tid & 15;
    const __half* bP = W + (size_t)bkr * DIMK + nb0 + nc * 8;
    const uint32_t bD0 = (uint32_t)A_ST + (uint32_t)(bkr * 256)
                       + ((uint32_t)((nc & 8) | ((nc ^ (bkr & 7)) & 7)) << 4);

    const int lt = lane >> 3, lr = lane & 7;
    const int mB  = (lt & 1) * 8 + lr;
    const int kbt = lt >> 1;
    const int sA  = (wm + mB) & 7;
    const uint32_t aLd = smBase + (uint32_t)((wm + mB) * 128);
    const int kB  = (lt & 1) * 8 + lr;
    const int s2  = kB & 7;
    const int ncT = (wn >> 3) + (lt >> 1);
    const uint32_t bLd = smBase + A_ST + (uint32_t)(kB * 256);
    uint32_t aXor[4], chnkB[4];
    #pragma unroll
    for (int ks = 0; ks < 4; ++ks)
        aXor[ks] = (uint32_t)(((2 * ks + kbt) ^ sA) << 4);
    #pragma unroll
    for (int np = 0; np < 4; ++np) {
        int nc2 = ncT + 2 * np;
        chnkB[np] = (uint32_t)(((nc2 & 8) | ((nc2 ^ s2) & 7)) << 4);
    }

    float acc[4][8][4];
    #pragma unroll
    for (int mt = 0; mt < 4; ++mt)
        #pragma unroll
        for (int nt = 0; nt < 8; ++nt)
            #pragma unroll
            for (int q = 0; q < 4; ++q) acc[mt][nt][q] = 0.f;

    ISSUE_CP(0u, 0);
    ISSUE_CP((uint32_t)STG_B, BK);

    uint32_t stO = 0;
    int kNext = 2 * BK;
    for (int c = 0; c < NCH; ++c) {
        if (c < NCH - 1)
            asm volatile("cp.async.wait_group 1;" ::: "memory");
        else
            asm volatile("cp.async.wait_group 0;" ::: "memory");
        __syncthreads();

        unsigned a0[4][4], a1[4][4], b0[8][2], b1[8][2];
        LDFRAG(a0, b0, 0);

        if (c + 2 < NCH) {
            uint32_t cpO = (stO >= (uint32_t)STG_B) ? stO - (uint32_t)STG_B
                                                    : stO + 2u * (uint32_t)STG_B;
            ISSUE_CP(cpO, kNext);
            kNext += BK;
        } else {
            asm volatile("cp.async.commit_group;" ::: "memory");
        }

        LDFRAG(a1, b1, 1);
        MMAB(a0, b0);
        LDFRAG(a0, b0, 2);
        MMAB(a1, b1);
        LDFRAG(a1, b1, 3);
        MMAB(a0, b0);
        MMAB(a1, b1);

        stO = (stO == 2u * (uint32_t)STG_B) ? 0u : stO + (uint32_t)STG_B;
    }

    #pragma unroll
    for (int mt = 0; mt < 4; ++mt) {
        int r0 = rb + wm + mt * 16 + qr;
        int r1 = r0 + 8;
        float g0 = 1.f, g1 = 1.f;
        if (MODE == 1 && !SH) { g0 = g_gate[r0]; g1 = g_gate[r1]; }
        #pragma unroll
        for (int nt = 0; nt < 8; ++nt) {
            int gcol = nb0 + wn + nt * 8 + 2 * qc;
            float b0v = Bv[gcol];
            float b1v = Bv[gcol + 1];
            float c00 = acc[mt][nt][0] + b0v;
            float c01 = acc[mt][nt][1] + b1v;
            float c10 = acc[mt][nt][2] + b0v;
            float c11 = acc[mt][nt][3] + b1v;
            if (MODE == 0) {
                __half2 h0 = __floats2half2_rn(gelu_exact(c00), gelu_exact(c01));
                __half2 h1 = __floats2half2_rn(gelu_exact(c10), gelu_exact(c11));
                *(__half2*)(&g_Hh[(size_t)r0 * DIMK + gcol]) = h0;
                *(__half2*)(&g_Hh[(size_t)r1 * DIMK + gcol]) = h1;
            } else if (SH) {
                int tok0 = r0 - SHBASE, tok1 = r1 - SHBASE;
                float2 x0 = *(const float2*)(xp + (size_t)tok0 * DIMK + gcol);
                float2 x1 = *(const float2*)(xp + (size_t)tok1 * DIMK + gcol);
                float2 v0 = make_float2(x0.x + c00, x0.y + c01);
                float2 v1 = make_float2(x1.x + c10, x1.y + c11);
                *(float2*)(outp + (size_t)tok0 * DIMK + gcol) = v0;
                *(float2*)(outp + (size_t)tok1 * DIMK + gcol) = v1;
            } else {
                __half2 h0 = __floats2half2_rn(g0 * c00, g0 * c01);
                __half2 h1 = __floats2half2_rn(g1 * c10, g1 * c11);
                *(__half2*)(&g_Yh[(size_t)r0 * DIMK + gcol]) = h0;
                *(__half2*)(&g_Yh[(size_t)r1 * DIMK + gcol]) = h1;
            }
        }
    }
}

// ---------------- finalize ----------------
__global__ void finalize_kernel(float* __restrict__ out)
{
    int idx = blockIdx.x * 256 + threadIdx.x;
    int t = idx >> 8;
    int q = (idx & 255) * 4;
    float4 r = *(const float4*)(out + (size_t)t * DIMK + q);
    #pragma unroll
    for (int k = 0; k < 3; ++k) {
        int s = g_slot[t * 3 + k];
        uint2 u = *(const uint2*)(&g_Yh[(size_t)s * DIMK + q]);
        __half2 h0 = *(__half2*)&u.x;
        __half2 h1 = *(__half2*)&u.y;
        float2 f0 = __half22float2(h0);
        float2 f1 = __half22float2(h1);
        r.x += f0.x; r.y += f0.y; r.z += f1.x; r.w += f1.y;
    }
    *(float4*)(out + (size_t)t * DIMK + q) = r;
}

// ---------------- launch ----------------
extern "C" void kernel_launch(void* const* d_in, const int* in_sizes, int n_in,
                              void* d_out, int out_size)
{
    const float* x   = (const float*)d_in[0];
    const float* ws1 = (const float*)d_in[1];
    const float* bs1 = (const float*)d_in[2];
    const float* ws2 = (const float*)d_in[3];
    const float* bs2 = (const float*)d_in[4];
    const float* We1 = (const float*)d_in[5];
    const float* Be1 = (const float*)d_in[6];
    const float* We2 = (const float*)d_in[7];
    const float* Be2 = (const float*)d_in[8];
    const float* Wr  = (const float*)d_in[9];
    const float* br  = (const float*)d_in[10];
    float* out = (float*)d_out;

    static cudaStream_t sB = 0, sD = 0;
    static cudaEvent_t evRoot = 0, evXsh = 0, evW1rt = 0, evW2rt = 0, evRt = 0;
    static bool init_done = false;
    if (!init_done) {
        cudaFuncSetAttribute(ffn_kernel<0,0>,
                             cudaFuncAttributeMaxDynamicSharedMemorySize, DYN_SMEM);
        cudaFuncSetAttribute(ffn_kernel<1,0>,
                             cudaFuncAttributeMaxDynamicSharedMemorySize, DYN_SMEM);
        cudaFuncSetAttribute(ffn_kernel<0,1>,
                             cudaFuncAttributeMaxDynamicSharedMemorySize, DYN_SMEM);
        cudaFuncSetAttribute(ffn_kernel<1,1>,
                             cudaFuncAttributeMaxDynamicSharedMemorySize, DYN_SMEM);
        int prLo = 0, prHi = 0;
        cudaDeviceGetStreamPriorityRange(&prLo, &prHi);
        cudaStreamCreateWithPriority(&sB, cudaStreamNonBlocking, prHi); // routing
        cudaStreamCreateWithPriority(&sD, cudaStreamNonBlocking, prLo); // convs
        cudaEventCreateWithFlags(&evRoot, cudaEventDisableTiming);
        cudaEventCreateWithFlags(&evXsh, cudaEventDisableTiming);
        cudaEventCreateWithFlags(&evW1rt, cudaEventDisableTiming);
        cudaEventCreateWithFlags(&evW2rt, cudaEventDisableTiming);
        cudaEventCreateWithFlags(&evRt, cudaEventDisableTiming);
        init_done = true;
    }

    cudaEventRecord(evRoot, 0);
    cudaStreamWaitEvent(sB, evRoot, 0);
    cudaStreamWaitEvent(sD, evRoot, 0);

    // stream B (high prio): routing chain
    init_kernel<<<(SHBASE + 255) / 256, 256, 0, sB>>>();
    router_kernel<<<T_TOK / 16, 256, 0, sB>>>(x, Wr, br);
    fill_kernel<<<T_TOK / 256, 256, 0, sB>>>();

    // stream D (low prio): routed weight conversions
    {
        size_t nr = (size_t)NE * DIMK * DIMK / 4;
        conv_w1rt_kernel<<<(unsigned)((nr + 255) / 256), 256, 0, sD>>>(We1);
        cudaEventRecord(evW1rt, sD);
        conv_w2rt_kernel<<<(unsigned)((nr + 255) / 256), 256, 0, sD>>>(We2);
        cudaEventRecord(evW2rt, sD);
    }

    // main: x + shared slices, shared-expert FFN
    {
        size_t n4 = (size_t)T_TOK * DIMK / 4 + 2 * ((size_t)DIMK * DIMK / 4);
        conv_xsh_kernel<<<(unsigned)((n4 + 255) / 256), 256>>>(x, ws1, ws2);
    }
    cudaEventRecord(evXsh, 0);

    dim3 gSh(SHT, DIMK / BN);
    ffn_kernel<0,1><<<gSh, 128, DYN_SMEM>>>(bs1, Be1, x, out);
    ffn_kernel<1,1><<<gSh, 128, DYN_SMEM>>>(bs2, Be2, x, out);

    // stream B: routed FFNs
    cudaStreamWaitEvent(sB, evXsh, 0);
    cudaStreamWaitEvent(sB, evW1rt, 0);
    dim3 gRt(MAXT_RT, DIMK / BN);
    ffn_kernel<0,0><<<gRt, 128, DYN_SMEM, sB>>>(bs1, Be1, x, out);
    cudaStreamWaitEvent(sB, evW2rt, 0);
    ffn_kernel<1,0><<<gRt, 128, DYN_SMEM, sB>>>(bs2, Be2, x, out);
    cudaEventRecord(evRt, sB);

    // main: join routed, finalize
    cudaStreamWaitEvent(0, evRt, 0);
    finalize_kernel<<<T_TOK, 256>>>(out);
}